// round 16
// baseline (speedup 1.0000x reference)
#include <cuda_runtime.h>
#include <cuda_bf16.h>
#include <cstdint>

// Problem constants (fixed by the dataset)
#define M_ROWS 1024     // B*T_NEW
#define CDIM   2048
#define HHEADS 16
#define DHEAD  128
#define TPAST  2048
#define TNEW   128
#define TTOT   2176
#define BATCH  8

// ---------------------------------------------------------------------------
// Scratch (no cudaMalloc allowed)
// g_xr / g_WT / g_attn are stored with the k-dimension PERMUTED within each
// 8-float group: k -> (k&~7) | ((k&3)<<1) | ((k>>2)&1).  Both GEMM operands
// share the permutation, so fragments (and results) are bit-identical.
// ---------------------------------------------------------------------------
__device__ float g_Q[M_ROWS * CDIM];       // 8 MB (standard layout)
__device__ float g_attn[M_ROWS * CDIM];    // 8 MB (tf32-rounded, k-permuted)
__device__ float g_xr[M_ROWS * CDIM];      // 8 MB (tf32-rounded, k-permuted)
__device__ float g_WT[4ull * CDIM * CDIM]; // 64 MB (transposed+rounded, k-permuted)

__device__ __forceinline__ float tf32r(float x) {
    float y;
    asm("cvt.rna.tf32.f32 %0, %1;" : "=f"(y) : "f"(x));
    return y;
}
__device__ __forceinline__ void mma8(float* c, const float* a, const float* b) {
    const uint32_t* A = reinterpret_cast<const uint32_t*>(a);
    const uint32_t* B = reinterpret_cast<const uint32_t*>(b);
    asm volatile(
        "mma.sync.aligned.m16n8k8.row.col.f32.tf32.tf32.f32 "
        "{%0,%1,%2,%3}, {%4,%5,%6,%7}, {%8,%9}, {%0,%1,%2,%3};\n"
        : "+f"(c[0]), "+f"(c[1]), "+f"(c[2]), "+f"(c[3])
        : "r"(A[0]), "r"(A[1]), "r"(A[2]), "r"(A[3]), "r"(B[0]), "r"(B[1]));
}
__device__ __forceinline__ void cp_async16(uint32_t saddr, const void* gaddr) {
    asm volatile("cp.async.ca.shared.global [%0], [%1], 16;\n" :: "r"(saddr), "l"(gaddr));
}

// ---------------------------------------------------------------------------
// Prep kernel: z<4 -> transpose+round W_z into g_WT (k-permuted);
// z==4 -> round x into g_xr (k-permuted); z==5 -> init out with bias
// grid (64,64,6), block (32,8)
// ---------------------------------------------------------------------------
__global__ void prep_kernel(
    const float* __restrict__ Wq, const float* __restrict__ Wk,
    const float* __restrict__ Wv, const float* __restrict__ Wo,
    const float* __restrict__ x, const float* __restrict__ bo,
    float* __restrict__ out)
{
    int z = blockIdx.z;
    int tx = threadIdx.x, ty = threadIdx.y;
    if (z >= 4) {
        int idx = blockIdx.y * 64 + blockIdx.x;
        if (idx >= 1024) return;
        size_t base = (size_t)idx * 2048 + (ty * 32 + tx) * 8;
        if (z == 4) {
            // round + permute one 8-float k-group per thread
            const float* src = x + base;
            float* dst = g_xr + base;
            float v[8];
#pragma unroll
            for (int j = 0; j < 8; j++) v[j] = tf32r(src[j]);
#pragma unroll
            for (int j = 0; j < 8; j++)
                dst[((j & 3) << 1) | (j >> 2)] = v[j];
        } else {
            const float4* bsrc = reinterpret_cast<const float4*>(bo + (base & (CDIM - 1)));
            float4* dst = reinterpret_cast<float4*>(out + base);
#pragma unroll
            for (int j = 0; j < 2; j++) dst[j] = bsrc[j];
        }
        return;
    }
    const float* W = (z == 0) ? Wq : (z == 1) ? Wk : (z == 2) ? Wv : Wo;
    float* WT = g_WT + (size_t)z * CDIM * CDIM;
    __shared__ float t[32][33];
    int x0 = blockIdx.x * 32, y0 = blockIdx.y * 32;  // y0 = k, x0 = n
#pragma unroll
    for (int j = 0; j < 4; j++)
        t[ty + 8 * j][tx] = tf32r(W[(size_t)(y0 + ty + 8 * j) * CDIM + x0 + tx]);
    __syncthreads();
    // store transposed with permuted k (k = y0 + tx)
    int kp = y0 + (tx & ~7) + (((tx & 3) << 1) | ((tx >> 2) & 1));
#pragma unroll
    for (int j = 0; j < 4; j++)
        WT[(size_t)(x0 + ty + 8 * j) * CDIM + kp] = t[tx][ty + 8 * j];
}

// ---------------------------------------------------------------------------
// cp.async 2-stage tf32 GEMM: CTA 128x128, warp 64x32, k-chunk 32.
// Operands k-permuted in global; smem rows stride GAS=40 floats (no XOR):
// a/b fragments are conflict-free LDS.64 (bank-pair 4(r+ks)+tg, distinct).
// smem: 2 stages x (A 20KB + B 20KB) = 80 KB -> 2 CTAs/SM.
// ---------------------------------------------------------------------------
#define GAS 40                          // smem row stride (floats)
#define GSTAGE_FLOATS (128 * GAS * 2)   // 10240 floats = 40 KB
#define GEMM_SMEM_BYTES (2 * GSTAGE_FLOATS * 4)   // 81920

__device__ __forceinline__ void fill_chunk(
    uint32_t sbase, int st, const float* __restrict__ Ap,
    const float* __restrict__ Bp, int kt)
{
    uint32_t base = sbase + st * (GSTAGE_FLOATS * 4);
    int tid = threadIdx.x;
#pragma unroll
    for (int i = 0; i < 4; i++) {
        int f = tid + i * 256;            // 0..1023
        int r = f >> 3, k4 = f & 7;
        uint32_t off = (uint32_t)(r * (GAS * 4) + k4 * 16);
        cp_async16(base + off,                 Ap + (size_t)r * CDIM + kt + k4 * 4);
        cp_async16(base + 128 * GAS * 4 + off, Bp + (size_t)r * CDIM + kt + k4 * 4);
    }
    asm volatile("cp.async.commit_group;\n");
}

__device__ __forceinline__ void gemm_core(
    const float* __restrict__ Ap, const float* __restrict__ Bp,
    const float* __restrict__ bias, float* __restrict__ out,
    int scatter, int bm, int bn, float* smem, int k0, int kch, int red)
{
    int tid = threadIdx.x;
    int lane = tid & 31, wid = tid >> 5;
    int g = lane >> 2, tg = lane & 3;
    int wr = (wid >> 2) * 64;
    int wc = (wid & 3) * 32;
    uint32_t sbase = (uint32_t)__cvta_generic_to_shared(smem);

    float acc[4][4][4];
#pragma unroll
    for (int i = 0; i < 4; i++)
#pragma unroll
        for (int j = 0; j < 4; j++)
#pragma unroll
            for (int k = 0; k < 4; k++) acc[i][j][k] = 0.f;

    fill_chunk(sbase, 0, Ap, Bp, k0);
    fill_chunk(sbase, 1, Ap, Bp, k0 + 32);
    asm volatile("cp.async.wait_group 1;\n");
    __syncthreads();

    for (int i = 0; i < kch; i++) {
        int st = i & 1;
        const float* sA = smem + st * GSTAGE_FLOATS;
        const float* sB = sA + 128 * GAS;

#pragma unroll
        for (int ks = 0; ks < 4; ks++) {
            int c = ks * 8 + 2 * tg;         // permuted pair (k=tg, k=tg+4)
            float a[4][4];
#pragma unroll
            for (int mi = 0; mi < 4; mi++) {
                int r0 = (wr + mi * 16 + g) * GAS;
                float2 la = *reinterpret_cast<const float2*>(&sA[r0 + c]);
                float2 lb = *reinterpret_cast<const float2*>(&sA[r0 + 8 * GAS + c]);
                a[mi][0] = la.x; a[mi][1] = lb.x;
                a[mi][2] = la.y; a[mi][3] = lb.y;
            }
            float b[4][2];
#pragma unroll
            for (int ni = 0; ni < 4; ni++) {
                float2 bb = *reinterpret_cast<const float2*>(
                    &sB[(wc + ni * 8 + g) * GAS + c]);
                b[ni][0] = bb.x; b[ni][1] = bb.y;
            }
#pragma unroll
            for (int mi = 0; mi < 4; mi++)
#pragma unroll
                for (int ni = 0; ni < 4; ni++)
                    mma8(acc[mi][ni], a[mi], b[ni]);
        }

        __syncthreads();
        if (i + 2 < kch) fill_chunk(sbase, st, Ap, Bp, k0 + (i + 2) * 32);
        if (i + 1 < kch) {
            if (i + 2 < kch) asm volatile("cp.async.wait_group 1;\n");
            else             asm volatile("cp.async.wait_group 0;\n");
            __syncthreads();
        }
    }

#pragma unroll
    for (int mi = 0; mi < 4; mi++) {
#pragma unroll
        for (int ni = 0; ni < 4; ni++) {
            int row0 = bm + wr + mi * 16 + g;
            int col0 = bn + wc + ni * 8 + 2 * tg;
#pragma unroll
            for (int e = 0; e < 4; e++) {
                int row = row0 + ((e >= 2) ? 8 : 0);
                int col = col0 + (e & 1);
                float v = acc[mi][ni][e];
                if (red) {
                    atomicAdd(&out[(size_t)row * CDIM + col], v);
                } else if (!scatter) {
                    out[(size_t)row * CDIM + col] = v + bias[col];
                } else {
                    int b_ = row >> 7, t_ = row & 127;
                    int h_ = col >> 7, d_ = col & 127;
                    out[((size_t)(b_ * HHEADS + h_) * TTOT + TPAST + t_) * DHEAD + d_] = v + bias[col];
                }
            }
        }
    }
}

// ---------------------------------------------------------------------------
// Fused: 512 CTAs; role = bid&3 (0=Q,1=K,2=V GEMM, 3=past copy)
// ---------------------------------------------------------------------------
__global__ __launch_bounds__(256, 2) void fused_qkv_copy(
    const float* __restrict__ bq, const float* __restrict__ bk, const float* __restrict__ bv,
    const float* __restrict__ Kp, const float* __restrict__ Vp,
    float* __restrict__ gQ, float* __restrict__ Kout, float* __restrict__ Vout)
{
    extern __shared__ __align__(16) float smem[];
    int lin = blockIdx.x;
    int role = lin & 3;
    int t = lin >> 2;  // 0..127

    if (role == 3) {
        const float4* Ks = reinterpret_cast<const float4*>(Kp) + (size_t)t * (TPAST * DHEAD / 4);
        const float4* Vs = reinterpret_cast<const float4*>(Vp) + (size_t)t * (TPAST * DHEAD / 4);
        float4* Kd = reinterpret_cast<float4*>(Kout) + (size_t)t * (TTOT * DHEAD / 4);
        float4* Vd = reinterpret_cast<float4*>(Vout) + (size_t)t * (TTOT * DHEAD / 4);
        for (int i = threadIdx.x; i < TPAST * DHEAD / 4; i += 256) {
            Kd[i] = Ks[i];
            Vd[i] = Vs[i];
        }
        return;
    }

    int bm = (t >> 4) * 128, bn = (t & 15) * 128;
    const float* Ap = g_xr + (size_t)bm * CDIM;
    const float* Bp = g_WT + (size_t)role * CDIM * CDIM + (size_t)bn * CDIM;
    if (role == 0)      gemm_core(Ap, Bp, bq, gQ,   0, bm, bn, smem, 0, 64, 0);
    else if (role == 1) gemm_core(Ap, Bp, bk, Kout, 1, bm, bn, smem, 0, 64, 0);
    else                gemm_core(Ap, Bp, bv, Vout, 1, bm, bn, smem, 0, 64, 0);
}

// gemm_wo split-K x2: 256 CTAs; tile = bid>>1, kslice = bid&1; RED.ADD epilogue
__global__ __launch_bounds__(256, 2) void gemm_wo(float* __restrict__ out)
{
    extern __shared__ __align__(16) float smem[];
    int t = blockIdx.x;
    int tile = t >> 1, ksl = t & 1;
    int bm = (tile >> 4) * 128, bn = (tile & 15) * 128;
    gemm_core(g_attn + (size_t)bm * CDIM,
              g_WT + 3ull * CDIM * CDIM + (size_t)bn * CDIM,
              nullptr, out, 0, bm, bn, smem, ksl * 1024, 32, 1);
}

// ---------------------------------------------------------------------------
// Flash attention: one CTA per (b,h), 8 warps x 16 query rows.
// Q: fragments hoisted to registers.  K: 64-row subtiles double-buffered,
// register-staged (LDG->RNA->STS), permuted-k @136 (LDS.64 b-frags).
// V: cp.async @136 (conflict-free PV).  P in registers via shuffles.
// Epilogue writes g_attn with PERMUTED k (consumed by gemm_wo).
// smem = sK0(64)+sK1(64)+sV(128) @136 = 139,264 B.
// ---------------------------------------------------------------------------
#define SKS 136
#define SVS 136
#define ATTN_SMEM_BYTES (256 * 136 * 4)   // 139264

__global__ __launch_bounds__(256) void attn_kernel(
    const float* __restrict__ Kc, const float* __restrict__ Vc)
{
    extern __shared__ float sm[];
    float* sK0 = sm;                        // 64 rows @ SKS (permuted k)
    float* sK1 = sm + 64 * SKS;             // 64 rows @ SKS (permuted k)
    float* sV  = sm + 128 * SKS;            // 128 rows @ SVS

    int tid = threadIdx.x, lane = tid & 31, wid = tid >> 5;
    int g = lane >> 2, tg = lane & 3;
    int bh = blockIdx.x, b = bh >> 4, h = bh & 15;
    const float qscale = 0.08838834764831845f;  // 1/sqrt(128)

    uint32_t svu = (uint32_t)__cvta_generic_to_shared(sV);

    const float* Kbh = Kc + (size_t)bh * TTOT * DHEAD;
    const float* Vbh = Vc + (size_t)bh * TTOT * DHEAD;

    int r0 = wid * 16;

    // ---- prologue ----
    float4 rk[8];
#pragma unroll
    for (int i = 0; i < 8; i++) {
        int f = tid + i * 256;
        int r = f >> 5, c4 = (f & 31) * 4;
        rk[i] = *reinterpret_cast<const float4*>(&Kbh[(size_t)r * DHEAD + c4]);
    }
#pragma unroll
    for (int i = 0; i < 16; i++) {
        int f = tid + i * 256;
        int r = f >> 5, c4 = (f & 31) * 4;
        cp_async16(svu + (uint32_t)(r * SVS + c4) * 4, &Vbh[(size_t)r * DHEAD + c4]);
    }
    asm volatile("cp.async.commit_group;\n");

    // Q fragments -> registers (scaled, RNA tf32)
    float qa[16][4];
    {
        const float* q0 = g_Q + (size_t)(b * TNEW + r0 + g) * CDIM + h * DHEAD;
        const float* q1 = q0 + 8 * CDIM;
#pragma unroll
        for (int ks = 0; ks < 16; ks++) {
            qa[ks][0] = tf32r(q0[ks * 8 + tg] * qscale);
            qa[ks][1] = tf32r(q1[ks * 8 + tg] * qscale);
            qa[ks][2] = tf32r(q0[ks * 8 + tg + 4] * qscale);
            qa[ks][3] = tf32r(q1[ks * 8 + tg + 4] * qscale);
        }
    }

    // STS K(0) -> sK0 (RNA, permuted k)
#pragma unroll
    for (int i = 0; i < 8; i++) {
        int f = tid + i * 256;
        int r = f >> 5, c4 = (f & 31) * 4;
        float v[4] = {tf32r(rk[i].x), tf32r(rk[i].y), tf32r(rk[i].z), tf32r(rk[i].w)};
#pragma unroll
        for (int j = 0; j < 4; j++) {
            int k = c4 + j;
            int p = (k & ~7) + ((k & 3) << 1) + ((k >> 2) & 1);
            sK0[r * SKS + p] = v[j];
        }
    }
#pragma unroll
    for (int i = 0; i < 8; i++) {
        int f = tid + i * 256;
        int r = f >> 5, c4 = (f & 31) * 4;
        rk[i] = *reinterpret_cast<const float4*>(&Kbh[(size_t)(64 + r) * DHEAD + c4]);
    }

    float m0 = -1e30f, m1 = -1e30f, l0 = 0.f, l1 = 0.f;
    float O[16][4];
#pragma unroll
    for (int nt = 0; nt < 16; nt++)
#pragma unroll
        for (int e = 0; e < 4; e++) O[nt][e] = 0.f;

    int srcA = 4 * g + (tg >> 1);
    int srcB = srcA + 2;
    bool oddt = (tg & 1) != 0;

    // ---- main loop over 34 subtiles of 64 keys ----
    for (int s = 0; s < 34; s++) {
        float* sKc = (s & 1) ? sK1 : sK0;

        if (s < 33) {
            float* sKn = (s & 1) ? sK0 : sK1;
#pragma unroll
            for (int i = 0; i < 8; i++) {
                int f = tid + i * 256;
                int r = f >> 5, c4 = (f & 31) * 4;
                float v[4] = {tf32r(rk[i].x), tf32r(rk[i].y), tf32r(rk[i].z), tf32r(rk[i].w)};
#pragma unroll
                for (int j = 0; j < 4; j++) {
                    int k = c4 + j;
                    int p = (k & ~7) + ((k & 3) << 1) + ((k >> 2) & 1);
                    sKn[r * SKS + p] = v[j];
                }
            }
        }
        if (s < 32) {
#pragma unroll
            for (int i = 0; i < 8; i++) {
                int f = tid + i * 256;
                int r = f >> 5, c4 = (f & 31) * 4;
                rk[i] = *reinterpret_cast<const float4*>(
                    &Kbh[(size_t)((s + 2) * 64 + r) * DHEAD + c4]);
            }
        }
        if ((s & 1) == 0) asm volatile("cp.async.wait_group 0;\n");  // V(s/2) ready
        __syncthreads();

        // S = Q K_sub^T
        float S[8][4];
#pragma unroll
        for (int nt = 0; nt < 8; nt++)
#pragma unroll
            for (int e = 0; e < 4; e++) S[nt][e] = 0.f;

#pragma unroll
        for (int ks = 0; ks < 16; ks++) {
#pragma unroll
            for (int nt = 0; nt < 8; nt++) {
                float2 bb = *reinterpret_cast<const float2*>(
                    &sKc[(nt * 8 + g) * SKS + ks * 8 + 2 * tg]);
                float bv[2] = {bb.x, bb.y};
                mma8(S[nt], qa[ks], bv);
            }
        }

        if (s >= 32) {
            int cb = (s - 32) * 64;
            int q0r = r0 + g, q1r = q0r + 8;
#pragma unroll
            for (int nt = 0; nt < 8; nt++) {
                int c0 = cb + nt * 8 + 2 * tg;
                if (c0 > q0r) S[nt][0] = -1e30f;
                if (c0 + 1 > q0r) S[nt][1] = -1e30f;
                if (c0 > q1r) S[nt][2] = -1e30f;
                if (c0 + 1 > q1r) S[nt][3] = -1e30f;
            }
        }

        // online softmax over this 64-key slab
        float mx0 = -1e30f, mx1 = -1e30f;
#pragma unroll
        for (int nt = 0; nt < 8; nt++) {
            mx0 = fmaxf(mx0, fmaxf(S[nt][0], S[nt][1]));
            mx1 = fmaxf(mx1, fmaxf(S[nt][2], S[nt][3]));
        }
        mx0 = fmaxf(mx0, __shfl_xor_sync(0xffffffffu, mx0, 1));
        mx0 = fmaxf(mx0, __shfl_xor_sync(0xffffffffu, mx0, 2));
        mx1 = fmaxf(mx1, __shfl_xor_sync(0xffffffffu, mx1, 1));
        mx1 = fmaxf(mx1, __shfl_xor_sync(0xffffffffu, mx1, 2));

        float mn0 = fmaxf(m0, mx0), mn1 = fmaxf(m1, mx1);
        float sc0 = __expf(m0 - mn0), sc1 = __expf(m1 - mn1);
        float rs0 = 0.f, rs1 = 0.f;
#pragma unroll
        for (int nt = 0; nt < 8; nt++) {
            S[nt][0] = __expf(S[nt][0] - mn0);
            S[nt][1] = __expf(S[nt][1] - mn0);
            S[nt][2] = __expf(S[nt][2] - mn1);
            S[nt][3] = __expf(S[nt][3] - mn1);
            rs0 += S[nt][0] + S[nt][1];
            rs1 += S[nt][2] + S[nt][3];
        }
        rs0 += __shfl_xor_sync(0xffffffffu, rs0, 1);
        rs0 += __shfl_xor_sync(0xffffffffu, rs0, 2);
        rs1 += __shfl_xor_sync(0xffffffffu, rs1, 1);
        rs1 += __shfl_xor_sync(0xffffffffu, rs1, 2);

        l0 = l0 * sc0 + rs0;
        l1 = l1 * sc1 + rs1;
#pragma unroll
        for (int nt = 0; nt < 16; nt++) {
            O[nt][0] *= sc0; O[nt][1] *= sc0;
            O[nt][2] *= sc1; O[nt][3] *= sc1;
        }
        m0 = mn0; m1 = mn1;

#pragma unroll
        for (int nt = 0; nt < 8; nt++)
#pragma unroll
            for (int e = 0; e < 4; e++) S[nt][e] = tf32r(S[nt][e]);

        // O += P V : P acc-fragments -> A-fragments via shuffles
        int vrow0 = (s & 1) * 64;
#pragma unroll
        for (int kv = 0; kv < 8; kv++) {
            float e0 = __shfl_sync(0xffffffffu, S[kv][0], srcA);
            float o0 = __shfl_sync(0xffffffffu, S[kv][1], srcA);
            float e1 = __shfl_sync(0xffffffffu, S[kv][2], srcA);
            float o1 = __shfl_sync(0xffffffffu, S[kv][3], srcA);
            float f0 = __shfl_sync(0xffffffffu, S[kv][0], srcB);
            float p0 = __shfl_sync(0xffffffffu, S[kv][1], srcB);
            float f1 = __shfl_sync(0xffffffffu, S[kv][2], srcB);
            float p1 = __shfl_sync(0xffffffffu, S[kv][3], srcB);
            float a[4];
            a[0] = oddt ? o0 : e0;
            a[1] = oddt ? o1 : e1;
            a[2] = oddt ? p0 : f0;
            a[3] = oddt ? p1 : f1;
#pragma unroll
            for (int nt = 0; nt < 16; nt++) {
                float bb[2];
                bb[0] = sV[(vrow0 + kv * 8 + tg) * SVS + nt * 8 + g];
                bb[1] = sV[(vrow0 + kv * 8 + tg + 4) * SVS + nt * 8 + g];
                mma8(O[nt], a, bb);
            }
        }

        __syncthreads();

        if ((s & 1) == 1 && s < 33) {
            int vt = (s >> 1) + 1;
#pragma unroll
            for (int i = 0; i < 16; i++) {
                int f = tid + i * 256;
                int r = f >> 5, c4 = (f & 31) * 4;
                cp_async16(svu + (uint32_t)(r * SVS + c4) * 4,
                           &Vbh[(size_t)(vt * 128 + r) * DHEAD + c4]);
            }
            asm volatile("cp.async.commit_group;\n");
        }
    }

    // Epilogue: write g_attn with PERMUTED k (k-dim of the Wo GEMM)
    float i0 = 1.f / l0, i1 = 1.f / l1;
    int e0 = 2 * tg, e1 = 2 * tg + 1;
    int p0 = ((e0 & 3) << 1) | (e0 >> 2);
    int p1 = ((e1 & 3) << 1) | (e1 >> 2);
#pragma unroll
    for (int nt = 0; nt < 16; nt++) {
        int colg = h * DHEAD + nt * 8;
        float* o0 = &g_attn[(size_t)(b * TNEW + r0 + g) * CDIM + colg];
        o0[p0] = tf32r(O[nt][0] * i0);
        o0[p1] = tf32r(O[nt][1] * i0);
        float* o1 = &g_attn[(size_t)(b * TNEW + r0 + g + 8) * CDIM + colg];
        o1[p0] = tf32r(O[nt][2] * i1);
        o1[p1] = tf32r(O[nt][3] * i1);
    }
}

// ---------------------------------------------------------------------------
extern "C" void kernel_launch(void* const* d_in, const int* in_sizes, int n_in,
                              void* d_out, int out_size)
{
    const float* x  = (const float*)d_in[0];
    const float* Kp = (const float*)d_in[1];
    const float* Vp = (const float*)d_in[2];
    const float* Wq = (const float*)d_in[3];
    const float* bq = (const float*)d_in[4];
    const float* Wk = (const float*)d_in[5];
    const float* bk = (const float*)d_in[6];
    const float* Wv = (const float*)d_in[7];
    const float* bv = (const float*)d_in[8];
    const float* Wo = (const float*)d_in[9];
    const float* bo = (const float*)d_in[10];

    float* out  = (float*)d_out;
    float* Kout = out + (size_t)M_ROWS * CDIM;
    float* Vout = Kout + (size_t)BATCH * HHEADS * TTOT * DHEAD;

    float* gQ;
    cudaGetSymbolAddress((void**)&gQ, g_Q);

    cudaFuncSetAttribute(attn_kernel, cudaFuncAttributeMaxDynamicSharedMemorySize, ATTN_SMEM_BYTES);
    cudaFuncSetAttribute(fused_qkv_copy, cudaFuncAttributeMaxDynamicSharedMemorySize, GEMM_SMEM_BYTES);
    cudaFuncSetAttribute(gemm_wo, cudaFuncAttributeMaxDynamicSharedMemorySize, GEMM_SMEM_BYTES);

    // Phase 0: transpose+round weights (k-permuted), round x (k-permuted),
    // init out with bias
    prep_kernel<<<dim3(64, 64, 6), dim3(32, 8)>>>(Wq, Wk, Wv, Wo, x, bo, out);

    // Phase 1: fused QKV GEMMs + past-KV copy (role-interleaved)
    fused_qkv_copy<<<512, 256, GEMM_SMEM_BYTES>>>(bq, bk, bv, Kp, Vp, gQ, Kout, Vout);

    // Phase 2: attention
    attn_kernel<<<BATCH * HHEADS, 256, ATTN_SMEM_BYTES>>>(Kout, Vout);

    // Phase 3: output projection (split-K x2, deterministic RED.ADD)
    gemm_wo<<<256, 256, GEMM_SMEM_BYTES>>>(out);
}